// round 15
// baseline (speedup 1.0000x reference)
#include <cuda_runtime.h>
#include <cuda_fp16.h>
#include <cstdint>

#define NTOK 2048
#define DDIM 1024
#define NEXP 8
#define SEG  2048

// ---------------- scratch (static device globals; no allocation) -------------
__device__ __half g_x16[NTOK * DDIM];
__device__ __half g_hsh16[NTOK * DDIM];
__device__ __half g_hex16[NEXP * SEG * DDIM];
__device__ __half g_w1_16[NEXP * DDIM * DDIM];
__device__ __half g_w2_16[NEXP * DDIM * DDIM];
__device__ __half g_cfc16[DDIM * DDIM];
__device__ __half g_cpj16[DDIM * DDIM];
__device__ int   g_cnt[NEXP];
__device__ int   g_tok[NEXP * SEG];
__device__ float g_gw[NEXP * SEG];

// region boundaries (elements)
#define C0 2097152u    // x
#define C1 10485760u   // + w1
#define C2 18874368u   // + w2
#define C3 19922944u   // + cfc
#define C4 20971520u   // + cproj

// ---------------- fused convert: fp32 -> fp16 for all operands ---------------
__global__ void convert_all(const float* __restrict__ x,
                            const float* __restrict__ w1,
                            const float* __restrict__ w2,
                            const float* __restrict__ cfc,
                            const float* __restrict__ cproj) {
    if (blockIdx.x == 0 && threadIdx.x < NEXP) g_cnt[threadIdx.x] = 0;
    size_t base = (size_t)blockIdx.x * 2048 + (size_t)threadIdx.x * 8;
    const float* src;
    __half* dst;
    size_t off;
    if (base < C0)      { src = x;     dst = g_x16;   off = base; }
    else if (base < C1) { src = w1;    dst = g_w1_16; off = base - C0; }
    else if (base < C2) { src = w2;    dst = g_w2_16; off = base - C1; }
    else if (base < C3) { src = cfc;   dst = g_cfc16; off = base - C2; }
    else                { src = cproj; dst = g_cpj16; off = base - C3; }
    float4 v0 = __ldcs(reinterpret_cast<const float4*>(src + off));
    float4 v1 = __ldcs(reinterpret_cast<const float4*>(src + off + 4));
    __half2 h[4];
    h[0] = __floats2half2_rn(v0.x, v0.y);
    h[1] = __floats2half2_rn(v0.z, v0.w);
    h[2] = __floats2half2_rn(v1.x, v1.y);
    h[3] = __floats2half2_rn(v1.z, v1.w);
    *reinterpret_cast<uint4*>(dst + off) = *reinterpret_cast<uint4*>(h);
}

// ---------------- router: exact fp32 logits, top-2, sigmoid gating -----------
__global__ void router_kernel(const float* __restrict__ x,
                              const float* __restrict__ gate_w,
                              const float* __restrict__ lb_bias) {
    __shared__ float lg[NEXP];
    int n = blockIdx.x;
    int e = threadIdx.x >> 5, lane = threadIdx.x & 31;
    const float* xr = x + (size_t)n * DDIM;
    const float* w  = gate_w + (size_t)e * DDIM;
    float s = 0.f;
    #pragma unroll 4
    for (int d = lane; d < DDIM; d += 32) s += xr[d] * w[d];
    #pragma unroll
    for (int o = 16; o; o >>= 1) s += __shfl_xor_sync(0xffffffffu, s, o);
    if (lane == 0) lg[e] = s;
    __syncthreads();
    if (threadIdx.x == 0) {
        float b1v = -1e30f; int b1 = 0;
        #pragma unroll
        for (int i = 0; i < NEXP; i++) {
            float v = lg[i] + lb_bias[i];
            if (v > b1v) { b1v = v; b1 = i; }
        }
        float b2v = -1e30f; int b2 = 0;
        #pragma unroll
        for (int i = 0; i < NEXP; i++) {
            if (i == b1) continue;
            float v = lg[i] + lb_bias[i];
            if (v > b2v) { b2v = v; b2 = i; }
        }
        float w1v = 1.f / (1.f + expf(-lg[b1]));
        float w2v = 1.f / (1.f + expf(-lg[b2]));
        float inv = 1.f / (w1v + w2v + 1e-6f);
        w1v *= inv; w2v *= inv;
        int p1 = atomicAdd(&g_cnt[b1], 1);
        g_tok[b1 * SEG + p1] = n; g_gw[b1 * SEG + p1] = w1v;
        int p2 = atomicAdd(&g_cnt[b2], 1);
        g_tok[b2 * SEG + p2] = n; g_gw[b2 * SEG + p2] = w2v;
    }
}

// ---------------- pipelined fp16 mma.sync GEMM -------------------------------
// BM=128, BN=128, BK=32; 8 warps (4x2), warp tile 32x64; 3-stage cp.async;
// 256 threads/CTA, 2 CTAs/SM. cp.async issue is SCATTERED: the four 16B
// LDGSTS per thread per stage are emitted one at a time between the
// j-iterations of the s=0 MMA block (burst depth 1), minimizing cross-CTA
// L1tex wavefront-queue collisions after the block barrier.
// PHASE 1: y<16 shared GEMM1 (x*cfc), y>=16 expert GEMM1 (gather x * w1[e]);
//          epilogue relu^2 -> fp16 hidden.
// PHASE 2: y<16 shared GEMM2 (hsh*cproj), y>=16 expert GEMM2 (hex*w2[e]);
//          epilogue red.global.add.v2.f32 into pre-zeroed out.

#define ROWB    80
#define REG_B   10240
#define STAGE_B 20480
#define SMEM_GEMM (3 * STAGE_B)

#define CP16(sm, gp) \
    asm volatile("cp.async.cg.shared.global [%0], [%1], 16;" \
                 :: "r"(sm), "l"(gp) : "memory")
#define CP_COMMIT() asm volatile("cp.async.commit_group;" ::: "memory")
#define CP_WAIT1()  asm volatile("cp.async.wait_group 1;" ::: "memory")

#define LDSM4(r, a) \
    asm volatile("ldmatrix.sync.aligned.m8n8.x4.shared.b16 {%0,%1,%2,%3}, [%4];" \
                 : "=r"((r)[0]), "=r"((r)[1]), "=r"((r)[2]), "=r"((r)[3]) \
                 : "r"(a))

#define MMA_F16(c, a, bb0, bb1)                                                \
    asm volatile(                                                              \
        "mma.sync.aligned.m16n8k16.row.col.f32.f16.f16.f32 "                   \
        "{%0,%1,%2,%3},{%4,%5,%6,%7},{%8,%9},{%0,%1,%2,%3};\n"                 \
        : "+f"((c)[0]), "+f"((c)[1]), "+f"((c)[2]), "+f"((c)[3])               \
        : "r"((a)[0]), "r"((a)[1]), "r"((a)[2]), "r"((a)[3]),                  \
          "r"(bb0), "r"(bb1))

__device__ __forceinline__ uint32_t smem_u32(const void* p) {
    uint32_t a;
    asm("{ .reg .u64 t; cvta.to.shared.u64 t, %1; cvt.u32.u64 %0, t; }"
        : "=r"(a) : "l"(p));
    return a;
}

__device__ __forceinline__ void red_add2(float* p, float a, float b) {
    asm volatile("red.global.add.v2.f32 [%0], {%1, %2};"
                 :: "l"(p), "f"(a), "f"(b) : "memory");
}

template <int PHASE>
__global__ __launch_bounds__(256, 2)
void gemm_mma(float* __restrict__ C) {
    extern __shared__ char dsm[];
    const int tid = threadIdx.x;
    const int wid = tid >> 5, lane = tid & 31;
    const int wm = (wid & 3) * 32, wn = (wid >> 2) * 64;

    const bool sh = (blockIdx.y < 16);
    int e = 0, m0, cnt;
    const __half *A, *B;
    if (sh) {
        m0 = blockIdx.y * 128;
        cnt = NTOK;
        if (PHASE == 1) { A = g_x16;   B = g_cfc16; }
        else            { A = g_hsh16; B = g_cpj16; }
    } else {
        int yb = blockIdx.y - 16;
        e = yb >> 4;
        m0 = (yb & 15) * 128;
        cnt = g_cnt[e];
        if (m0 >= cnt) return;
        size_t wo = (size_t)e * DDIM * DDIM;
        if (PHASE == 1) { A = g_x16; B = g_w1_16 + wo; }
        else { A = g_hex16 + (size_t)e * SEG * DDIM; B = g_w2_16 + wo; }
    }
    const int n0 = blockIdx.x * 128;

    // per-thread cp.async assignment: row lr, two 16B chunks
    const int lr = tid >> 1;
    const int lc0 = (tid & 1) * 2;
    const __half* pA;
    if (PHASE == 1 && !sh) {
        int rr = m0 + lr;
        int tok = g_tok[e * SEG + (rr < cnt ? rr : 0)];
        pA = g_x16 + (size_t)tok * DDIM;
    } else {
        pA = A + (size_t)(m0 + lr) * DDIM;
    }
    const __half* pB = B + (size_t)(n0 + lr) * DDIM;

    const uint32_t su = smem_u32(dsm);
    const uint32_t wbase = lr * ROWB + lc0 * 16;

    const uint32_t aoff = (uint32_t)((wm + (lane & 15)) * ROWB + (lane >> 4) * 16);
    const int brow = (lane & 7) | ((lane & 16) >> 1);
    const uint32_t boff = (uint32_t)((wn + brow) * ROWB + ((lane >> 3) & 1) * 16);

    float acc[2][8][4];
    #pragma unroll
    for (int mi = 0; mi < 2; mi++)
        #pragma unroll
        for (int ni = 0; ni < 8; ni++)
            #pragma unroll
            for (int j = 0; j < 4; j++) acc[mi][ni][j] = 0.f;

    // individual 16B chunk issues (burst depth 1)
    #define ISS_A0(kt, st) CP16(su + (st) * STAGE_B + wbase, \
                                pA + (kt) * 32 + lc0 * 8)
    #define ISS_A1(kt, st) CP16(su + (st) * STAGE_B + wbase + 16, \
                                pA + (kt) * 32 + lc0 * 8 + 8)
    #define ISS_B0(kt, st) CP16(su + (st) * STAGE_B + wbase + REG_B, \
                                pB + (kt) * 32 + lc0 * 8)
    #define ISS_B1(kt, st) CP16(su + (st) * STAGE_B + wbase + REG_B + 16, \
                                pB + (kt) * 32 + lc0 * 8 + 8)

    ISS_A0(0, 0); ISS_A1(0, 0); ISS_B0(0, 0); ISS_B1(0, 0); CP_COMMIT();
    ISS_A0(1, 1); ISS_A1(1, 1); ISS_B0(1, 1); ISS_B1(1, 1); CP_COMMIT();

    int st = 0;
    for (int kt = 0; kt < 32; kt++) {
        CP_WAIT1();
        __syncthreads();
        int st2 = st + 2; if (st2 >= 3) st2 -= 3;
        const bool pf = (kt < 30);

        const uint32_t sA = su + st * STAGE_B;
        const uint32_t sB = sA + REG_B;

        // ---- s = 0 compute with scattered prefetch issues ----
        {
            uint32_t ah[2][4];
            #pragma unroll
            for (int mi = 0; mi < 2; mi++)
                LDSM4(ah[mi], sA + aoff + mi * (16 * ROWB));

            uint32_t bh[4];
            LDSM4(bh, sB + boff + 0 * (16 * ROWB));
            MMA_F16(acc[0][0], ah[0], bh[0], bh[1]);
            MMA_F16(acc[0][1], ah[0], bh[2], bh[3]);
            MMA_F16(acc[1][0], ah[1], bh[0], bh[1]);
            MMA_F16(acc[1][1], ah[1], bh[2], bh[3]);
            if (pf) ISS_A0(kt + 2, st2);

            LDSM4(bh, sB + boff + 1 * (16 * ROWB));
            MMA_F16(acc[0][2], ah[0], bh[0], bh[1]);
            MMA_F16(acc[0][3], ah[0], bh[2], bh[3]);
            MMA_F16(acc[1][2], ah[1], bh[0], bh[1]);
            MMA_F16(acc[1][3], ah[1], bh[2], bh[3]);
            if (pf) ISS_A1(kt + 2, st2);

            LDSM4(bh, sB + boff + 2 * (16 * ROWB));
            MMA_F16(acc[0][4], ah[0], bh[0], bh[1]);
            MMA_F16(acc[0][5], ah[0], bh[2], bh[3]);
            MMA_F16(acc[1][4], ah[1], bh[0], bh[1]);
            MMA_F16(acc[1][5], ah[1], bh[2], bh[3]);
            if (pf) ISS_B0(kt + 2, st2);

            LDSM4(bh, sB + boff + 3 * (16 * ROWB));
            MMA_F16(acc[0][6], ah[0], bh[0], bh[1]);
            MMA_F16(acc[0][7], ah[0], bh[2], bh[3]);
            MMA_F16(acc[1][6], ah[1], bh[0], bh[1]);
            MMA_F16(acc[1][7], ah[1], bh[2], bh[3]);
            if (pf) ISS_B1(kt + 2, st2);
        }
        CP_COMMIT();

        // ---- s = 1 compute ----
        {
            uint32_t ah[2][4];
            #pragma unroll
            for (int mi = 0; mi < 2; mi++)
                LDSM4(ah[mi], sA + aoff + mi * (16 * ROWB) + 32);
            #pragma unroll
            for (int j = 0; j < 4; j++) {
                uint32_t bh[4];
                LDSM4(bh, sB + boff + j * (16 * ROWB) + 32);
                #pragma unroll
                for (int mi = 0; mi < 2; mi++) {
                    MMA_F16(acc[mi][2 * j],     ah[mi], bh[0], bh[1]);
                    MMA_F16(acc[mi][2 * j + 1], ah[mi], bh[2], bh[3]);
                }
            }
        }
        st++; if (st >= 3) st = 0;
    }
    #undef ISS_A0
    #undef ISS_A1
    #undef ISS_B0
    #undef ISS_B1

    // ---- epilogue ----
    const int g = lane >> 2, q = lane & 3;
    #pragma unroll
    for (int mi = 0; mi < 2; mi++) {
        int rr0 = m0 + wm + mi * 16 + g;
        int rr1 = rr0 + 8;
        int tok0 = rr0, tok1 = rr1;
        float gw0 = 1.f, gw1 = 1.f;
        if (PHASE == 2 && !sh) {
            if (rr0 < cnt) { tok0 = g_tok[e * SEG + rr0]; gw0 = g_gw[e * SEG + rr0]; }
            if (rr1 < cnt) { tok1 = g_tok[e * SEG + rr1]; gw1 = g_gw[e * SEG + rr1]; }
        }
        #pragma unroll
        for (int ni = 0; ni < 8; ni++) {
            int c = n0 + wn + ni * 8 + 2 * q;
            float v0 = acc[mi][ni][0], v1 = acc[mi][ni][1];
            float v2 = acc[mi][ni][2], v3 = acc[mi][ni][3];
            if (PHASE == 1) {
                __half* H = sh ? g_hsh16 : g_hex16 + (size_t)e * SEG * DDIM;
                if (rr0 < cnt) {
                    float f0 = fmaxf(v0, 0.f); f0 *= f0;
                    float f1 = fmaxf(v1, 0.f); f1 *= f1;
                    *reinterpret_cast<__half2*>(H + (size_t)rr0 * DDIM + c) =
                        __floats2half2_rn(f0, f1);
                }
                if (rr1 < cnt) {
                    float f2 = fmaxf(v2, 0.f); f2 *= f2;
                    float f3 = fmaxf(v3, 0.f); f3 *= f3;
                    *reinterpret_cast<__half2*>(H + (size_t)rr1 * DDIM + c) =
                        __floats2half2_rn(f2, f3);
                }
            } else {
                if (rr0 < cnt)
                    red_add2(C + (size_t)tok0 * DDIM + c, gw0 * v0, gw0 * v1);
                if (rr1 < cnt)
                    red_add2(C + (size_t)tok1 * DDIM + c, gw1 * v2, gw1 * v3);
            }
        }
    }
}

// ---------------- launch -----------------------------------------------------
extern "C" void kernel_launch(void* const* d_in, const int* in_sizes, int n_in,
                              void* d_out, int out_size) {
    const float* x      = (const float*)d_in[0];
    const float* gate_w = (const float*)d_in[1];
    const float* lbias  = (const float*)d_in[2];
    const float* w1     = (const float*)d_in[3];
    const float* w2     = (const float*)d_in[4];
    const float* cfc    = (const float*)d_in[5];
    const float* cproj  = (const float*)d_in[6];
    float* out = (float*)d_out;

    cudaFuncSetAttribute(gemm_mma<1>, cudaFuncAttributeMaxDynamicSharedMemorySize, SMEM_GEMM);
    cudaFuncSetAttribute(gemm_mma<2>, cudaFuncAttributeMaxDynamicSharedMemorySize, SMEM_GEMM);

    cudaMemsetAsync(out, 0, (size_t)out_size * sizeof(float));
    convert_all<<<10240, 256>>>(x, w1, w2, cfc, cproj);
    router_kernel<<<NTOK, 256>>>(x, gate_w, lbias);

    // phase 1: y 0..15 shared GEMM1, y 16..143 expert GEMM1
    gemm_mma<1><<<dim3(8, 144), 256, SMEM_GEMM>>>(nullptr);
    // phase 2: fused shared GEMM2 + expert GEMM2, atomic accumulate into out
    gemm_mma<2><<<dim3(8, 144), 256, SMEM_GEMM>>>(out);
}

// round 16
// speedup vs baseline: 1.0741x; 1.0741x over previous
#include <cuda_runtime.h>
#include <cuda_fp16.h>
#include <cstdint>

#define NTOK 2048
#define DDIM 1024
#define NEXP 8
#define SEG  2048

// ---------------- scratch (static device globals; no allocation) -------------
__device__ __half g_x16[NTOK * DDIM];
__device__ __half g_hsh16[NTOK * DDIM];
__device__ __half g_hex16[NEXP * SEG * DDIM];
__device__ __half g_w1_16[NEXP * DDIM * DDIM];
__device__ __half g_w2_16[NEXP * DDIM * DDIM];
__device__ __half g_cfc16[DDIM * DDIM];
__device__ __half g_cpj16[DDIM * DDIM];
__device__ int   g_cnt[NEXP];
__device__ int   g_tok[NEXP * SEG];
__device__ float g_gw[NEXP * SEG];

// convert_all region boundaries (elements): x, w1, cfc only
#define D0 2097152u    // x
#define D1 10485760u   // + w1
#define D2 11534336u   // + cfc   (5632 blocks * 2048)

// phase-1 inline convert: w2 then cproj (4608 blocks * 2048 = 9437184)
#define W2_ELEMS 8388608u

// ---------------- convert: fp32 -> fp16 for x, w1, cfc -----------------------
__global__ void convert_all(const float* __restrict__ x,
                            const float* __restrict__ w1,
                            const float* __restrict__ cfc) {
    if (blockIdx.x == 0 && threadIdx.x < NEXP) g_cnt[threadIdx.x] = 0;
    size_t base = (size_t)blockIdx.x * 2048 + (size_t)threadIdx.x * 8;
    const float* src;
    __half* dst;
    size_t off;
    if (base < D0)      { src = x;   dst = g_x16;   off = base; }
    else if (base < D1) { src = w1;  dst = g_w1_16; off = base - D0; }
    else                { src = cfc; dst = g_cfc16; off = base - D1; }
    float4 v0 = __ldcs(reinterpret_cast<const float4*>(src + off));
    float4 v1 = __ldcs(reinterpret_cast<const float4*>(src + off + 4));
    __half2 h[4];
    h[0] = __floats2half2_rn(v0.x, v0.y);
    h[1] = __floats2half2_rn(v0.z, v0.w);
    h[2] = __floats2half2_rn(v1.x, v1.y);
    h[3] = __floats2half2_rn(v1.z, v1.w);
    *reinterpret_cast<uint4*>(dst + off) = *reinterpret_cast<uint4*>(h);
}

// ---------------- router: exact fp32 logits, top-2, sigmoid gating -----------
__global__ void router_kernel(const float* __restrict__ x,
                              const float* __restrict__ gate_w,
                              const float* __restrict__ lb_bias) {
    __shared__ float lg[NEXP];
    int n = blockIdx.x;
    int e = threadIdx.x >> 5, lane = threadIdx.x & 31;
    const float* xr = x + (size_t)n * DDIM;
    const float* w  = gate_w + (size_t)e * DDIM;
    float s = 0.f;
    #pragma unroll 4
    for (int d = lane; d < DDIM; d += 32) s += xr[d] * w[d];
    #pragma unroll
    for (int o = 16; o; o >>= 1) s += __shfl_xor_sync(0xffffffffu, s, o);
    if (lane == 0) lg[e] = s;
    __syncthreads();
    if (threadIdx.x == 0) {
        float b1v = -1e30f; int b1 = 0;
        #pragma unroll
        for (int i = 0; i < NEXP; i++) {
            float v = lg[i] + lb_bias[i];
            if (v > b1v) { b1v = v; b1 = i; }
        }
        float b2v = -1e30f; int b2 = 0;
        #pragma unroll
        for (int i = 0; i < NEXP; i++) {
            if (i == b1) continue;
            float v = lg[i] + lb_bias[i];
            if (v > b2v) { b2v = v; b2 = i; }
        }
        float w1v = 1.f / (1.f + expf(-lg[b1]));
        float w2v = 1.f / (1.f + expf(-lg[b2]));
        float inv = 1.f / (w1v + w2v + 1e-6f);
        w1v *= inv; w2v *= inv;
        int p1 = atomicAdd(&g_cnt[b1], 1);
        g_tok[b1 * SEG + p1] = n; g_gw[b1 * SEG + p1] = w1v;
        int p2 = atomicAdd(&g_cnt[b2], 1);
        g_tok[b2 * SEG + p2] = n; g_gw[b2 * SEG + p2] = w2v;
    }
}

// ---------------- pipelined fp16 mma.sync GEMM -------------------------------
// BM=128, BN=128, BK=32; 8 warps (4x2), warp tile 32x64; 3-stage cp.async;
// 256 threads/CTA, 2 CTAs/SM. 2-way staggered cp.async (A-half after the
// barrier, B-half between the two k=16 sub-steps) — round-14 validated.
// PHASE 1: y<16 shared GEMM1 (x*cfc), 16<=y<144 expert GEMM1; epilogue
//   relu^2 -> fp16 hidden. y>=144: inline fp32->fp16 convert of w2/cproj
//   (fills phase-1's idle second wave; completes before phase 2 starts).
// PHASE 2: y<16 shared GEMM2 (hsh*cproj), y>=16 expert GEMM2 (hex*w2[e]);
//          epilogue red.global.add.v2.f32 into pre-zeroed out.

#define ROWB    80
#define REG_B   10240
#define STAGE_B 20480
#define SMEM_GEMM (3 * STAGE_B)

#define CP16(sm, gp) \
    asm volatile("cp.async.cg.shared.global [%0], [%1], 16;" \
                 :: "r"(sm), "l"(gp) : "memory")
#define CP_COMMIT() asm volatile("cp.async.commit_group;" ::: "memory")
#define CP_WAIT1()  asm volatile("cp.async.wait_group 1;" ::: "memory")

#define LDSM4(r, a) \
    asm volatile("ldmatrix.sync.aligned.m8n8.x4.shared.b16 {%0,%1,%2,%3}, [%4];" \
                 : "=r"((r)[0]), "=r"((r)[1]), "=r"((r)[2]), "=r"((r)[3]) \
                 : "r"(a))

#define MMA_F16(c, a, bb0, bb1)                                                \
    asm volatile(                                                              \
        "mma.sync.aligned.m16n8k16.row.col.f32.f16.f16.f32 "                   \
        "{%0,%1,%2,%3},{%4,%5,%6,%7},{%8,%9},{%0,%1,%2,%3};\n"                 \
        : "+f"((c)[0]), "+f"((c)[1]), "+f"((c)[2]), "+f"((c)[3])               \
        : "r"((a)[0]), "r"((a)[1]), "r"((a)[2]), "r"((a)[3]),                  \
          "r"(bb0), "r"(bb1))

__device__ __forceinline__ uint32_t smem_u32(const void* p) {
    uint32_t a;
    asm("{ .reg .u64 t; cvta.to.shared.u64 t, %1; cvt.u32.u64 %0, t; }"
        : "=r"(a) : "l"(p));
    return a;
}

__device__ __forceinline__ void red_add2(float* p, float a, float b) {
    asm volatile("red.global.add.v2.f32 [%0], {%1, %2};"
                 :: "l"(p), "f"(a), "f"(b) : "memory");
}

template <int PHASE>
__global__ __launch_bounds__(256, 2)
void gemm_mma(float* __restrict__ C,
              const float* __restrict__ w2_src,
              const float* __restrict__ cpj_src) {
    extern __shared__ char dsm[];
    const int tid = threadIdx.x;

    // ---- phase-1 trailing blocks: inline convert of w2 / cproj ----
    if (PHASE == 1 && blockIdx.y >= 144) {
        size_t c = ((size_t)(blockIdx.y - 144) * 8 + blockIdx.x) * 2048
                   + (size_t)tid * 8;
        const float* src;
        __half* dst;
        size_t off;
        if (c < W2_ELEMS) { src = w2_src;  dst = g_w2_16;  off = c; }
        else              { src = cpj_src; dst = g_cpj16;  off = c - W2_ELEMS; }
        float4 v0 = __ldcs(reinterpret_cast<const float4*>(src + off));
        float4 v1 = __ldcs(reinterpret_cast<const float4*>(src + off + 4));
        __half2 h[4];
        h[0] = __floats2half2_rn(v0.x, v0.y);
        h[1] = __floats2half2_rn(v0.z, v0.w);
        h[2] = __floats2half2_rn(v1.x, v1.y);
        h[3] = __floats2half2_rn(v1.z, v1.w);
        *reinterpret_cast<uint4*>(dst + off) = *reinterpret_cast<uint4*>(h);
        return;
    }

    const int wid = tid >> 5, lane = tid & 31;
    const int wm = (wid & 3) * 32, wn = (wid >> 2) * 64;

    const bool sh = (blockIdx.y < 16);
    int e = 0, m0, cnt;
    const __half *A, *B;
    if (sh) {
        m0 = blockIdx.y * 128;
        cnt = NTOK;
        if (PHASE == 1) { A = g_x16;   B = g_cfc16; }
        else            { A = g_hsh16; B = g_cpj16; }
    } else {
        int yb = blockIdx.y - 16;
        e = yb >> 4;
        m0 = (yb & 15) * 128;
        cnt = g_cnt[e];
        if (m0 >= cnt) return;
        size_t wo = (size_t)e * DDIM * DDIM;
        if (PHASE == 1) { A = g_x16; B = g_w1_16 + wo; }
        else { A = g_hex16 + (size_t)e * SEG * DDIM; B = g_w2_16 + wo; }
    }
    const int n0 = blockIdx.x * 128;

    // per-thread cp.async assignment: row lr, two 16B chunks
    const int lr = tid >> 1;
    const int lc0 = (tid & 1) * 2;
    const __half* pA;
    if (PHASE == 1 && !sh) {
        int rr = m0 + lr;
        int tok = g_tok[e * SEG + (rr < cnt ? rr : 0)];
        pA = g_x16 + (size_t)tok * DDIM;
    } else {
        pA = A + (size_t)(m0 + lr) * DDIM;
    }
    const __half* pB = B + (size_t)(n0 + lr) * DDIM;

    const uint32_t su = smem_u32(dsm);
    const uint32_t wbase = lr * ROWB + lc0 * 16;

    const uint32_t aoff = (uint32_t)((wm + (lane & 15)) * ROWB + (lane >> 4) * 16);
    const int brow = (lane & 7) | ((lane & 16) >> 1);
    const uint32_t boff = (uint32_t)((wn + brow) * ROWB + ((lane >> 3) & 1) * 16);

    float acc[2][8][4];
    #pragma unroll
    for (int mi = 0; mi < 2; mi++)
        #pragma unroll
        for (int ni = 0; ni < 8; ni++)
            #pragma unroll
            for (int j = 0; j < 4; j++) acc[mi][ni][j] = 0.f;

    #define ISSUE_A(kt, st) do {                                               \
        uint32_t sb = su + (st) * STAGE_B + wbase;                             \
        const __half* ga = pA + (kt) * 32 + lc0 * 8;                           \
        CP16(sb, ga); CP16(sb + 16, ga + 8);                                   \
    } while (0)
    #define ISSUE_B(kt, st) do {                                               \
        uint32_t sb = su + (st) * STAGE_B + wbase;                             \
        const __half* gb = pB + (kt) * 32 + lc0 * 8;                           \
        CP16(sb + REG_B, gb); CP16(sb + REG_B + 16, gb + 8);                   \
    } while (0)

    ISSUE_A(0, 0); ISSUE_B(0, 0); CP_COMMIT();
    ISSUE_A(1, 1); ISSUE_B(1, 1); CP_COMMIT();

    int st = 0;
    for (int kt = 0; kt < 32; kt++) {
        CP_WAIT1();
        __syncthreads();
        int st2 = st + 2; if (st2 >= 3) st2 -= 3;
        // ---- first half-burst: A-region loads for stage kt+2 ----
        if (kt < 30) ISSUE_A(kt + 2, st2);

        const uint32_t sA = su + st * STAGE_B;
        const uint32_t sB = sA + REG_B;

        // ---- s = 0 compute ----
        {
            uint32_t ah[2][4];
            #pragma unroll
            for (int mi = 0; mi < 2; mi++)
                LDSM4(ah[mi], sA + aoff + mi * (16 * ROWB));
            #pragma unroll
            for (int j = 0; j < 4; j++) {
                uint32_t bh[4];
                LDSM4(bh, sB + boff + j * (16 * ROWB));
                #pragma unroll
                for (int mi = 0; mi < 2; mi++) {
                    MMA_F16(acc[mi][2 * j],     ah[mi], bh[0], bh[1]);
                    MMA_F16(acc[mi][2 * j + 1], ah[mi], bh[2], bh[3]);
                }
            }
        }

        // ---- second half-burst: B-region loads for stage kt+2 ----
        if (kt < 30) ISSUE_B(kt + 2, st2);
        CP_COMMIT();

        // ---- s = 1 compute ----
        {
            uint32_t ah[2][4];
            #pragma unroll
            for (int mi = 0; mi < 2; mi++)
                LDSM4(ah[mi], sA + aoff + mi * (16 * ROWB) + 32);
            #pragma unroll
            for (int j = 0; j < 4; j++) {
                uint32_t bh[4];
                LDSM4(bh, sB + boff + j * (16 * ROWB) + 32);
                #pragma unroll
                for (int mi = 0; mi < 2; mi++) {
                    MMA_F16(acc[mi][2 * j],     ah[mi], bh[0], bh[1]);
                    MMA_F16(acc[mi][2 * j + 1], ah[mi], bh[2], bh[3]);
                }
            }
        }
        st++; if (st >= 3) st = 0;
    }
    #undef ISSUE_A
    #undef ISSUE_B

    // ---- epilogue ----
    const int g = lane >> 2, q = lane & 3;
    #pragma unroll
    for (int mi = 0; mi < 2; mi++) {
        int rr0 = m0 + wm + mi * 16 + g;
        int rr1 = rr0 + 8;
        int tok0 = rr0, tok1 = rr1;
        float gw0 = 1.f, gw1 = 1.f;
        if (PHASE == 2 && !sh) {
            if (rr0 < cnt) { tok0 = g_tok[e * SEG + rr0]; gw0 = g_gw[e * SEG + rr0]; }
            if (rr1 < cnt) { tok1 = g_tok[e * SEG + rr1]; gw1 = g_gw[e * SEG + rr1]; }
        }
        #pragma unroll
        for (int ni = 0; ni < 8; ni++) {
            int c = n0 + wn + ni * 8 + 2 * q;
            float v0 = acc[mi][ni][0], v1 = acc[mi][ni][1];
            float v2 = acc[mi][ni][2], v3 = acc[mi][ni][3];
            if (PHASE == 1) {
                __half* H = sh ? g_hsh16 : g_hex16 + (size_t)e * SEG * DDIM;
                if (rr0 < cnt) {
                    float f0 = fmaxf(v0, 0.f); f0 *= f0;
                    float f1 = fmaxf(v1, 0.f); f1 *= f1;
                    *reinterpret_cast<__half2*>(H + (size_t)rr0 * DDIM + c) =
                        __floats2half2_rn(f0, f1);
                }
                if (rr1 < cnt) {
                    float f2 = fmaxf(v2, 0.f); f2 *= f2;
                    float f3 = fmaxf(v3, 0.f); f3 *= f3;
                    *reinterpret_cast<__half2*>(H + (size_t)rr1 * DDIM + c) =
                        __floats2half2_rn(f2, f3);
                }
            } else {
                if (rr0 < cnt)
                    red_add2(C + (size_t)tok0 * DDIM + c, gw0 * v0, gw0 * v1);
                if (rr1 < cnt)
                    red_add2(C + (size_t)tok1 * DDIM + c, gw1 * v2, gw1 * v3);
            }
        }
    }
}

// ---------------- launch -----------------------------------------------------
extern "C" void kernel_launch(void* const* d_in, const int* in_sizes, int n_in,
                              void* d_out, int out_size) {
    const float* x      = (const float*)d_in[0];
    const float* gate_w = (const float*)d_in[1];
    const float* lbias  = (const float*)d_in[2];
    const float* w1     = (const float*)d_in[3];
    const float* w2     = (const float*)d_in[4];
    const float* cfc    = (const float*)d_in[5];
    const float* cproj  = (const float*)d_in[6];
    float* out = (float*)d_out;

    cudaFuncSetAttribute(gemm_mma<1>, cudaFuncAttributeMaxDynamicSharedMemorySize, SMEM_GEMM);
    cudaFuncSetAttribute(gemm_mma<2>, cudaFuncAttributeMaxDynamicSharedMemorySize, SMEM_GEMM);

    cudaMemsetAsync(out, 0, (size_t)out_size * sizeof(float));
    // convert only what phase 1 needs (x, w1, cfc)
    convert_all<<<5632, 256>>>(x, w1, cfc);
    router_kernel<<<NTOK, 256>>>(x, gate_w, lbias);

    // phase 1: y 0..15 shared GEMM1, y 16..143 expert GEMM1,
    //          y 144..719 inline convert of w2/cproj (fills idle wave)
    gemm_mma<1><<<dim3(8, 720), 256, SMEM_GEMM>>>(nullptr, w2, cproj);
    // phase 2: fused shared GEMM2 + expert GEMM2, atomic accumulate into out
    gemm_mma<2><<<dim3(8, 144), 256, SMEM_GEMM>>>(out, nullptr, nullptr);
}